// round 12
// baseline (speedup 1.0000x reference)
#include <cuda_runtime.h>
#include <cuda_fp16.h>
#include <cstdint>

#define B_   2048
#define D_   4096
#define E_   512
#define NN_  8192
#define BN_EPS  1e-5f
#define COS_EPSF 1e-8f

// ---------------- scratch (__device__ globals; no allocations allowed) ----------------
__device__ float  g_psum[32][D_];
__device__ float  g_psq [32][D_];
__device__ float  g_scale[D_];
__device__ float  g_shift[D_];
__device__ __half g_vfn[B_ * D_];       // 17 MB (fp16 BN output)
__device__ float  g_pe [B_];
__device__ __half g_emb[B_ * E_];       // 2 MB (normalized, fp16)
__device__ __half g_nwn[NN_ * E_];      // 8 MB (normalized, fp16)
__device__ __half g_wr [E_ * D_];       // 4 MB (fp16 W)
__device__ float  g_part[4][B_ * E_];   // 16 MB split-K partials (fp32)

// ---------------- helpers ----------------
__device__ __forceinline__ void cp16(uint32_t dst, const void* src) {
    asm volatile("cp.async.cg.shared.global [%0], [%1], 16;" :: "r"(dst), "l"(src));
}
#define SW128(o) ((o) ^ (((o) >> 3) & 0x70))

#define LDSM4(r0, r1, r2, r3, a) \
    asm volatile("ldmatrix.sync.aligned.m8n8.x4.shared.b16 {%0,%1,%2,%3}, [%4];" \
                 : "=r"(r0), "=r"(r1), "=r"(r2), "=r"(r3) : "r"(a))

#define MMA16(d, av, b0v, b1v) \
    asm volatile("mma.sync.aligned.m16n8k16.row.col.f32.f16.f16.f32 " \
                 "{%0,%1,%2,%3}, {%4,%5,%6,%7}, {%8,%9}, {%0,%1,%2,%3};" \
                 : "+f"((d)[0]), "+f"((d)[1]), "+f"((d)[2]), "+f"((d)[3]) \
                 : "r"((av)[0]), "r"((av)[1]), "r"((av)[2]), "r"((av)[3]), \
                   "r"(b0v), "r"(b1v))

__device__ __forceinline__ uint32_t h2pack(float a, float b) {
    const __half2 h = __floats2half2_rn(a, b);
    return *reinterpret_cast<const uint32_t*>(&h);
}

// ---------------- BN partial column stats (deterministic) ----------------------------
__global__ void __launch_bounds__(256) k_stats(const float* __restrict__ vf) {
    const int bid = blockIdx.x;                  // 0..511
    const int c = (bid & 15) * 256 + threadIdx.x;
    const int chunk = bid >> 4;                  // 0..31
    const int r0 = chunk * 64;
    float s = 0.f, q = 0.f;
    #pragma unroll 4
    for (int r = 0; r < 64; r++) {
        float v = vf[(size_t)(r0 + r) * D_ + c];
        s += v; q += v * v;
    }
    g_psum[chunk][c] = s;
    g_psq [chunk][c] = q;
}

__global__ void k_stats_final(const float* __restrict__ gamma,
                              const float* __restrict__ beta) {
    const int c = blockIdx.x * 256 + threadIdx.x;
    float s = 0.f, q = 0.f;
    #pragma unroll
    for (int i = 0; i < 32; i++) { s += g_psum[i][c]; q += g_psq[i][c]; }
    const float mean = s * (1.0f / B_);
    const float var  = q * (1.0f / B_) - mean * mean;
    const float sc   = gamma[c] * rsqrtf(var + BN_EPS);
    g_scale[c] = sc;
    g_shift[c] = beta[c] - mean * sc;
}

// ---- mega pass: BN apply + p_e [0,2048) | W->fp16 [2048,3072) | nwn [3072,7168) -----
__global__ void __launch_bounds__(256) k_mega(const float* __restrict__ vf,
                                              const float* __restrict__ p,
                                              const float4* __restrict__ W,
                                              __half* __restrict__ Wr,
                                              const float4* __restrict__ nwfs,
                                              __half* __restrict__ nwn) {
    const int t = threadIdx.x;
    if (blockIdx.x < 2048) {
        const int row = blockIdx.x;
        const float4* v4  = (const float4*)(vf + (size_t)row * D_);
        const float4* p4  = (const float4*)(p  + (size_t)row * D_);
        const float4* sc4 = (const float4*)g_scale;
        const float4* sh4 = (const float4*)g_shift;
        uint2* o2 = (uint2*)(g_vfn + (size_t)row * D_);

        float dot = 0.f, nv = 0.f, np = 0.f;
        #pragma unroll
        for (int u = 0; u < 2; u++) {
            const int i0 = t + u * 512;
            const float4 va = __ldcs(&v4[i0]);
            const float4 vb = __ldcs(&v4[i0 + 256]);
            const float4 pa = __ldcs(&p4[i0]);
            const float4 pb = __ldcs(&p4[i0 + 256]);
            const float4 sa = sc4[i0], sb = sc4[i0 + 256];
            const float4 ha = sh4[i0], hb = sh4[i0 + 256];
            float4 xa, xb;
            xa.x = va.x * sa.x + ha.x; xa.y = va.y * sa.y + ha.y;
            xa.z = va.z * sa.z + ha.z; xa.w = va.w * sa.w + ha.w;
            xb.x = vb.x * sb.x + hb.x; xb.y = vb.y * sb.y + hb.y;
            xb.z = vb.z * sb.z + hb.z; xb.w = vb.w * sb.w + hb.w;
            uint2 ra, rb;
            ra.x = h2pack(xa.x, xa.y); ra.y = h2pack(xa.z, xa.w);
            rb.x = h2pack(xb.x, xb.y); rb.y = h2pack(xb.z, xb.w);
            o2[i0] = ra;
            o2[i0 + 256] = rb;
            dot += xa.x * pa.x + xa.y * pa.y + xa.z * pa.z + xa.w * pa.w;
            dot += xb.x * pb.x + xb.y * pb.y + xb.z * pb.z + xb.w * pb.w;
            nv  += xa.x * xa.x + xa.y * xa.y + xa.z * xa.z + xa.w * xa.w;
            nv  += xb.x * xb.x + xb.y * xb.y + xb.z * xb.z + xb.w * xb.w;
            np  += pa.x * pa.x + pa.y * pa.y + pa.z * pa.z + pa.w * pa.w;
            np  += pb.x * pb.x + pb.y * pb.y + pb.z * pb.z + pb.w * pb.w;
        }
        #pragma unroll
        for (int o = 16; o; o >>= 1) {
            dot += __shfl_down_sync(0xffffffffu, dot, o);
            nv  += __shfl_down_sync(0xffffffffu, nv,  o);
            np  += __shfl_down_sync(0xffffffffu, np,  o);
        }
        __shared__ float sd[8], sn[8], sp[8];
        const int lane = t & 31, w = t >> 5;
        if (lane == 0) { sd[w] = dot; sn[w] = nv; sp[w] = np; }
        __syncthreads();
        if (t == 0) {
            float Dv = 0.f, NV = 0.f, NP = 0.f;
            #pragma unroll
            for (int i = 0; i < 8; i++) { Dv += sd[i]; NV += sn[i]; NP += sp[i]; }
            g_pe[row] = Dv / (fmaxf(sqrtf(NV), COS_EPSF) * fmaxf(sqrtf(NP), COS_EPSF));
        }
    } else if (blockIdx.x < 3072) {
        const int gl = (blockIdx.x - 2048) * 256 + t;
        const float4 v0 = W[gl * 2], v1 = W[gl * 2 + 1];
        uint4 o;
        o.x = h2pack(v0.x, v0.y); o.y = h2pack(v0.z, v0.w);
        o.z = h2pack(v1.x, v1.y); o.w = h2pack(v1.z, v1.w);
        ((uint4*)Wr)[gl] = o;
    } else {
        const int seg = blockIdx.x - 3072;
        const int half = t >> 7;
        const int tt = t & 127;
        const int row = seg * 2 + half;
        const float4 v = nwfs[(size_t)row * 128 + tt];
        float s = v.x * v.x + v.y * v.y + v.z * v.z + v.w * v.w;
        #pragma unroll
        for (int o = 16; o; o >>= 1) s += __shfl_down_sync(0xffffffffu, s, o);
        __shared__ float ss[8];
        const int w = t >> 5;
        if ((t & 31) == 0) ss[w] = s;
        __syncthreads();
        const int b0 = half * 4;
        const float tot = ss[b0] + ss[b0 + 1] + ss[b0 + 2] + ss[b0 + 3];
        const float inv = 1.0f / fmaxf(sqrtf(tot), COS_EPSF);
        uint2 o;
        o.x = h2pack(v.x * inv, v.y * inv);
        o.y = h2pack(v.z * inv, v.w * inv);
        ((uint2*)(nwn + (size_t)row * E_))[tt] = o;
    }
}

// ---------------- split-K(4) reduce + bias + relu + rownorm -> fp16 g_emb ------------
__global__ void k_fuse_emb(const float* __restrict__ bias) {
    const int row = blockIdx.x;
    const int t = threadIdx.x;
    float4 s = make_float4(0.f, 0.f, 0.f, 0.f);
    #pragma unroll
    for (int p = 0; p < 4; p++) {
        const float4 v = *(const float4*)(&g_part[p][(size_t)row * E_ + t * 4]);
        s.x += v.x; s.y += v.y; s.z += v.z; s.w += v.w;
    }
    const float4 bq = ((const float4*)bias)[t];
    s.x = fmaxf(s.x + bq.x, 0.f);
    s.y = fmaxf(s.y + bq.y, 0.f);
    s.z = fmaxf(s.z + bq.z, 0.f);
    s.w = fmaxf(s.w + bq.w, 0.f);
    float nrm = s.x * s.x + s.y * s.y + s.z * s.z + s.w * s.w;
    #pragma unroll
    for (int o = 16; o; o >>= 1) nrm += __shfl_down_sync(0xffffffffu, nrm, o);
    __shared__ float ss[4];
    if ((t & 31) == 0) ss[t >> 5] = nrm;
    __syncthreads();
    const float tot = ss[0] + ss[1] + ss[2] + ss[3];
    const float inv = 1.0f / fmaxf(sqrtf(tot), COS_EPSF);
    uint2 o;
    o.x = h2pack(s.x * inv, s.y * inv);
    o.y = h2pack(s.z * inv, s.w * inv);
    ((uint2*)(g_emb + (size_t)row * E_))[t] = o;
}

// ---------------- fp16 mma.sync GEMM, templated tile (fine-grain balance) ------------
// 4 warps (128 thr), 2x2 warp grid, warp tile (BM/2)x(BN/2), BK=64, 3 stages.
// EPI 0: split-K partial store. EPI 1: out=C (+ pe broadcast), streaming stores.
template<int BM, int BN, int EPI, int OCC>
__global__ void __launch_bounds__(128, OCC)
k_mma(const __half* __restrict__ A, const __half* __restrict__ Bm,
      float* __restrict__ out, const float* __restrict__ pe,
      int M, int N, int K, int kcnt, size_t off2)
{
    constexpr int BK = 64, STAGES = 3, T = 128;
    constexpr int WM = BM / 2, WN = BN / 2;
    constexpr int MT = WM / 16, NT = WN / 8;     // MMA tiles per warp
    constexpr int ABYTES = BM * BK * 2;
    constexpr int BBYTES = BN * BK * 2;

    extern __shared__ char smem[];
    const uint32_t smA = (uint32_t)__cvta_generic_to_shared(smem);
    const uint32_t smB = smA + STAGES * ABYTES;

    const int t = threadIdx.x, lane = t & 31, warp = t >> 5;
    const int wm = warp >> 1, wn = warp & 1;      // 2x2 warps
    const int m0 = blockIdx.y * BM, n0 = blockIdx.x * BN;
    int k0 = 0;
    if (EPI == 0) { k0 = blockIdx.z * kcnt; out += (size_t)blockIdx.z * M * N; }

    // ldmatrix addressing (b16, 128B rows, SW128)
    const uint32_t xorv = (uint32_t)(lane & 7) * 16u;
    uint32_t aoff[MT], boff[NT / 2], acx[4], bcx[4];
    #pragma unroll
    for (int mt = 0; mt < MT; mt++)
        aoff[mt] = (uint32_t)((wm * WM + mt * 16 + (lane & 15)) * 128);
    #pragma unroll
    for (int p = 0; p < NT / 2; p++)
        boff[p] = (uint32_t)((wn * WN + p * 16 + (lane & 7) + ((lane & 16) >> 1)) * 128);
    #pragma unroll
    for (int ks = 0; ks < 4; ks++) {
        acx[ks] = ((uint32_t)(ks * 32) + (uint32_t)(lane & 16)) ^ xorv;
        bcx[ks] = ((uint32_t)(ks * 32) + (uint32_t)((lane & 8) << 1)) ^ xorv;
    }

    float acc[MT][NT][4];
    #pragma unroll
    for (int i = 0; i < MT; i++)
        #pragma unroll
        for (int j = 0; j < NT; j++)
            #pragma unroll
            for (int q = 0; q < 4; q++) acc[i][j][q] = 0.f;

    auto load_tile = [&](int stage, int kt) {
        const int kk = k0 + kt * BK;
        #pragma unroll
        for (int f = t; f < BM * 8; f += T) {
            const int r = f >> 3, c = f & 7;
            cp16(smA + (uint32_t)stage * ABYTES + SW128((uint32_t)(r * 128 + c * 16)),
                 A + (size_t)(m0 + r) * K + kk + c * 8);
        }
        #pragma unroll
        for (int f = t; f < BN * 8; f += T) {
            const int r = f >> 3, c = f & 7;
            cp16(smB + (uint32_t)stage * BBYTES + SW128((uint32_t)(r * 128 + c * 16)),
                 Bm + (size_t)(n0 + r) * K + kk + c * 8);
        }
        asm volatile("cp.async.commit_group;" ::: "memory");
    };

    const int KT = kcnt / BK;
    #pragma unroll
    for (int s = 0; s < STAGES - 1; s++) load_tile(s, s);

    #pragma unroll 1
    for (int kt = 0; kt < KT; kt++) {
        const int st = kt % STAGES;
        asm volatile("cp.async.wait_group %0;" :: "n"(STAGES - 2));
        __syncthreads();
        if (kt + STAGES - 1 < KT)
            load_tile((kt + STAGES - 1) % STAGES, kt + STAGES - 1);
        else
            asm volatile("cp.async.commit_group;" ::: "memory");

        const uint32_t aB = smA + (uint32_t)st * ABYTES;
        const uint32_t bB = smB + (uint32_t)st * BBYTES;
        #pragma unroll
        for (int ks = 0; ks < 4; ks++) {
            uint32_t a[MT][4], b[NT][2];
            #pragma unroll
            for (int mt = 0; mt < MT; mt++)
                LDSM4(a[mt][0], a[mt][1], a[mt][2], a[mt][3],
                      aB + aoff[mt] + acx[ks]);
            #pragma unroll
            for (int p = 0; p < NT / 2; p++)
                LDSM4(b[2 * p][0], b[2 * p][1], b[2 * p + 1][0], b[2 * p + 1][1],
                      bB + boff[p] + bcx[ks]);
            #pragma unroll
            for (int mt = 0; mt < MT; mt++)
                #pragma unroll
                for (int nt = 0; nt < NT; nt++)
                    MMA16(acc[mt][nt], a[mt], b[nt][0], b[nt][1]);
        }
    }

    // epilogue
    #pragma unroll
    for (int mt = 0; mt < MT; mt++) {
        const int r = m0 + wm * WM + mt * 16 + (lane >> 2);
        float pv0 = 0.f, pv1 = 0.f;
        if (EPI == 1) { pv0 = pe[r]; pv1 = pe[r + 8]; }
        #pragma unroll
        for (int nt = 0; nt < NT; nt++) {
            const int c = n0 + wn * WN + nt * 8 + 2 * (lane & 3);
            if (EPI == 0) {
                *(float2*)(out + (size_t)r * N + c) =
                    make_float2(acc[mt][nt][0], acc[mt][nt][1]);
                *(float2*)(out + (size_t)(r + 8) * N + c) =
                    make_float2(acc[mt][nt][2], acc[mt][nt][3]);
            } else {
                __stcs((float2*)(out + (size_t)r * N + c),
                       make_float2(acc[mt][nt][0], acc[mt][nt][1]));
                __stcs((float2*)(out + (size_t)(r + 8) * N + c),
                       make_float2(acc[mt][nt][2], acc[mt][nt][3]));
                __stcs((float2*)(out + off2 + (size_t)r * N + c), make_float2(pv0, pv0));
                __stcs((float2*)(out + off2 + (size_t)(r + 8) * N + c), make_float2(pv1, pv1));
            }
        }
    }
}

// ---------------- launch ----------------
extern "C" void kernel_launch(void* const* d_in, const int* in_sizes, int n_in,
                              void* d_out, int out_size)
{
    const float* vf    = (const float*)d_in[0];
    const float* pwfs  = (const float*)d_in[1];
    const float* nwfs  = (const float*)d_in[2];
    const float* gamma = (const float*)d_in[3];
    const float* beta  = (const float*)d_in[4];
    const float* W     = (const float*)d_in[5];
    const float* bias  = (const float*)d_in[6];
    float* out = (float*)d_out;

    __half *vfn_p, *emb_p, *nwn_p, *wr_p;
    float *pe_p, *part_p;
    cudaGetSymbolAddress((void**)&vfn_p,  g_vfn);
    cudaGetSymbolAddress((void**)&emb_p,  g_emb);
    cudaGetSymbolAddress((void**)&nwn_p,  g_nwn);
    cudaGetSymbolAddress((void**)&pe_p,   g_pe);
    cudaGetSymbolAddress((void**)&wr_p,   g_wr);
    cudaGetSymbolAddress((void**)&part_p, g_part);

    // 1: BN partial stats
    k_stats<<<512, 256>>>(vf);
    // 2: BN finalize
    k_stats_final<<<D_ / 256, 256>>>(gamma, beta);
    // 3: mega pass — BN apply + p_e | W->fp16 | nwn rownorm
    k_mega<<<2048 + 1024 + 4096, 256>>>(vf, pwfs, (const float4*)W, wr_p,
                                        (const float4*)nwfs, nwn_p);

    // 4: GEMM1 64x64 tiles, split-K=4 -> 1024 tiles (6.92/SM), occ 4
    constexpr int SM1 = 3 * (64 + 64) * 64 * 2;       // 48 KB
    cudaFuncSetAttribute(k_mma<64, 64, 0, 4>,
                         cudaFuncAttributeMaxDynamicSharedMemorySize, SM1);
    k_mma<64, 64, 0, 4><<<dim3(E_ / 64, B_ / 64, 4), 128, SM1>>>(
        vfn_p, wr_p, part_p, nullptr, B_, E_, D_, D_ / 4, 0);

    // 5: reduce 4 partials + bias + relu + rownorm -> fp16 emb
    k_fuse_emb<<<B_, 128>>>(bias);

    // 6: GEMM2 128x64 tiles -> 2048 tiles (13.84/SM), occ 3, fused p_e broadcast
    constexpr int SM2 = 3 * (128 + 64) * 64 * 2;      // 72 KB
    cudaFuncSetAttribute(k_mma<128, 64, 1, 3>,
                         cudaFuncAttributeMaxDynamicSharedMemorySize, SM2);
    const size_t off2 = (size_t)out_size / 2;
    k_mma<128, 64, 1, 3><<<dim3(NN_ / 64, B_ / 128), 128, SM2>>>(
        emb_p, nwn_p, out, pe_p, B_, NN_, E_, E_, off2);
}

// round 13
// speedup vs baseline: 1.0122x; 1.0122x over previous
#include <cuda_runtime.h>
#include <cuda_fp16.h>
#include <cstdint>

#define B_   2048
#define D_   4096
#define E_   512
#define NN_  8192
#define BN_EPS  1e-5f
#define COS_EPSF 1e-8f

// ---------------- scratch (__device__ globals; no allocations allowed) ----------------
__device__ float  g_psum[32][D_];
__device__ float  g_psq [32][D_];
__device__ float  g_scale[D_];
__device__ float  g_shift[D_];
__device__ __half g_vfn[B_ * D_];       // 17 MB (fp16 BN output)
__device__ float  g_pe [B_];
__device__ __half g_emb[B_ * E_];       // 2 MB (normalized, fp16)
__device__ __half g_nwn[NN_ * E_];      // 8 MB (normalized, fp16)
__device__ __half g_wr [E_ * D_];       // 4 MB (fp16 W)
__device__ float  g_part[4][B_ * E_];   // 16 MB split-K partials (fp32)

// ---------------- helpers ----------------
__device__ __forceinline__ void cp16(uint32_t dst, const void* src) {
    asm volatile("cp.async.cg.shared.global [%0], [%1], 16;" :: "r"(dst), "l"(src));
}
#define SW128(o) ((o) ^ (((o) >> 3) & 0x70))

#define LDSM4(r0, r1, r2, r3, a) \
    asm volatile("ldmatrix.sync.aligned.m8n8.x4.shared.b16 {%0,%1,%2,%3}, [%4];" \
                 : "=r"(r0), "=r"(r1), "=r"(r2), "=r"(r3) : "r"(a))

#define MMA16(d, av, b0v, b1v) \
    asm volatile("mma.sync.aligned.m16n8k16.row.col.f32.f16.f16.f32 " \
                 "{%0,%1,%2,%3}, {%4,%5,%6,%7}, {%8,%9}, {%0,%1,%2,%3};" \
                 : "+f"((d)[0]), "+f"((d)[1]), "+f"((d)[2]), "+f"((d)[3]) \
                 : "r"((av)[0]), "r"((av)[1]), "r"((av)[2]), "r"((av)[3]), \
                   "r"(b0v), "r"(b1v))

__device__ __forceinline__ uint32_t h2pack(float a, float b) {
    const __half2 h = __floats2half2_rn(a, b);
    return *reinterpret_cast<const uint32_t*>(&h);
}

// ---------------- BN partial column stats (deterministic) ----------------------------
__global__ void __launch_bounds__(256) k_stats(const float* __restrict__ vf) {
    const int bid = blockIdx.x;                  // 0..511
    const int c = (bid & 15) * 256 + threadIdx.x;
    const int chunk = bid >> 4;                  // 0..31
    const int r0 = chunk * 64;
    float s = 0.f, q = 0.f;
    #pragma unroll 4
    for (int r = 0; r < 64; r++) {
        float v = vf[(size_t)(r0 + r) * D_ + c];
        s += v; q += v * v;
    }
    g_psum[chunk][c] = s;
    g_psq [chunk][c] = q;
}

__global__ void k_stats_final(const float* __restrict__ gamma,
                              const float* __restrict__ beta) {
    const int c = blockIdx.x * 256 + threadIdx.x;
    float s = 0.f, q = 0.f;
    #pragma unroll
    for (int i = 0; i < 32; i++) { s += g_psum[i][c]; q += g_psq[i][c]; }
    const float mean = s * (1.0f / B_);
    const float var  = q * (1.0f / B_) - mean * mean;
    const float sc   = gamma[c] * rsqrtf(var + BN_EPS);
    g_scale[c] = sc;
    g_shift[c] = beta[c] - mean * sc;
}

// ---- mega pass: BN apply + p_e [0,2048) | W->fp16 [2048,3072) | nwn [3072,7168) -----
__global__ void __launch_bounds__(256) k_mega(const float* __restrict__ vf,
                                              const float* __restrict__ p,
                                              const float4* __restrict__ W,
                                              __half* __restrict__ Wr,
                                              const float4* __restrict__ nwfs,
                                              __half* __restrict__ nwn) {
    const int t = threadIdx.x;
    if (blockIdx.x < 2048) {
        const int row = blockIdx.x;
        const float4* v4  = (const float4*)(vf + (size_t)row * D_);
        const float4* p4  = (const float4*)(p  + (size_t)row * D_);
        const float4* sc4 = (const float4*)g_scale;
        const float4* sh4 = (const float4*)g_shift;
        uint2* o2 = (uint2*)(g_vfn + (size_t)row * D_);

        float dot = 0.f, nv = 0.f, np = 0.f;
        #pragma unroll
        for (int u = 0; u < 2; u++) {
            const int i0 = t + u * 512;
            const float4 va = __ldcs(&v4[i0]);
            const float4 vb = __ldcs(&v4[i0 + 256]);
            const float4 pa = __ldcs(&p4[i0]);
            const float4 pb = __ldcs(&p4[i0 + 256]);
            const float4 sa = sc4[i0], sb = sc4[i0 + 256];
            const float4 ha = sh4[i0], hb = sh4[i0 + 256];
            float4 xa, xb;
            xa.x = va.x * sa.x + ha.x; xa.y = va.y * sa.y + ha.y;
            xa.z = va.z * sa.z + ha.z; xa.w = va.w * sa.w + ha.w;
            xb.x = vb.x * sb.x + hb.x; xb.y = vb.y * sb.y + hb.y;
            xb.z = vb.z * sb.z + hb.z; xb.w = vb.w * sb.w + hb.w;
            uint2 ra, rb;
            ra.x = h2pack(xa.x, xa.y); ra.y = h2pack(xa.z, xa.w);
            rb.x = h2pack(xb.x, xb.y); rb.y = h2pack(xb.z, xb.w);
            o2[i0] = ra;
            o2[i0 + 256] = rb;
            dot += xa.x * pa.x + xa.y * pa.y + xa.z * pa.z + xa.w * pa.w;
            dot += xb.x * pb.x + xb.y * pb.y + xb.z * pb.z + xb.w * pb.w;
            nv  += xa.x * xa.x + xa.y * xa.y + xa.z * xa.z + xa.w * xa.w;
            nv  += xb.x * xb.x + xb.y * xb.y + xb.z * xb.z + xb.w * xb.w;
            np  += pa.x * pa.x + pa.y * pa.y + pa.z * pa.z + pa.w * pa.w;
            np  += pb.x * pb.x + pb.y * pb.y + pb.z * pb.z + pb.w * pb.w;
        }
        #pragma unroll
        for (int o = 16; o; o >>= 1) {
            dot += __shfl_down_sync(0xffffffffu, dot, o);
            nv  += __shfl_down_sync(0xffffffffu, nv,  o);
            np  += __shfl_down_sync(0xffffffffu, np,  o);
        }
        __shared__ float sd[8], sn[8], sp[8];
        const int lane = t & 31, w = t >> 5;
        if (lane == 0) { sd[w] = dot; sn[w] = nv; sp[w] = np; }
        __syncthreads();
        if (t == 0) {
            float Dv = 0.f, NV = 0.f, NP = 0.f;
            #pragma unroll
            for (int i = 0; i < 8; i++) { Dv += sd[i]; NV += sn[i]; NP += sp[i]; }
            g_pe[row] = Dv / (fmaxf(sqrtf(NV), COS_EPSF) * fmaxf(sqrtf(NP), COS_EPSF));
        }
    } else if (blockIdx.x < 3072) {
        const int gl = (blockIdx.x - 2048) * 256 + t;
        const float4 v0 = W[gl * 2], v1 = W[gl * 2 + 1];
        uint4 o;
        o.x = h2pack(v0.x, v0.y); o.y = h2pack(v0.z, v0.w);
        o.z = h2pack(v1.x, v1.y); o.w = h2pack(v1.z, v1.w);
        ((uint4*)Wr)[gl] = o;
    } else {
        const int seg = blockIdx.x - 3072;
        const int half = t >> 7;
        const int tt = t & 127;
        const int row = seg * 2 + half;
        const float4 v = nwfs[(size_t)row * 128 + tt];
        float s = v.x * v.x + v.y * v.y + v.z * v.z + v.w * v.w;
        #pragma unroll
        for (int o = 16; o; o >>= 1) s += __shfl_down_sync(0xffffffffu, s, o);
        __shared__ float ss[8];
        const int w = t >> 5;
        if ((t & 31) == 0) ss[w] = s;
        __syncthreads();
        const int b0 = half * 4;
        const float tot = ss[b0] + ss[b0 + 1] + ss[b0 + 2] + ss[b0 + 3];
        const float inv = 1.0f / fmaxf(sqrtf(tot), COS_EPSF);
        uint2 o;
        o.x = h2pack(v.x * inv, v.y * inv);
        o.y = h2pack(v.z * inv, v.w * inv);
        ((uint2*)(nwn + (size_t)row * E_))[tt] = o;
    }
}

// ---------------- split-K(4) reduce + bias + relu + rownorm -> fp16 g_emb ------------
__global__ void k_fuse_emb(const float* __restrict__ bias) {
    const int row = blockIdx.x;
    const int t = threadIdx.x;
    float4 s = make_float4(0.f, 0.f, 0.f, 0.f);
    #pragma unroll
    for (int p = 0; p < 4; p++) {
        const float4 v = *(const float4*)(&g_part[p][(size_t)row * E_ + t * 4]);
        s.x += v.x; s.y += v.y; s.z += v.z; s.w += v.w;
    }
    const float4 bq = ((const float4*)bias)[t];
    s.x = fmaxf(s.x + bq.x, 0.f);
    s.y = fmaxf(s.y + bq.y, 0.f);
    s.z = fmaxf(s.z + bq.z, 0.f);
    s.w = fmaxf(s.w + bq.w, 0.f);
    float nrm = s.x * s.x + s.y * s.y + s.z * s.z + s.w * s.w;
    #pragma unroll
    for (int o = 16; o; o >>= 1) nrm += __shfl_down_sync(0xffffffffu, nrm, o);
    __shared__ float ss[4];
    if ((t & 31) == 0) ss[t >> 5] = nrm;
    __syncthreads();
    const float tot = ss[0] + ss[1] + ss[2] + ss[3];
    const float inv = 1.0f / fmaxf(sqrtf(tot), COS_EPSF);
    uint2 o;
    o.x = h2pack(s.x * inv, s.y * inv);
    o.y = h2pack(s.z * inv, s.w * inv);
    ((uint2*)(g_emb + (size_t)row * E_))[t] = o;
}

// ---------------- fp16 mma.sync GEMM, templated tile -------------------------------
// 4 warps (128 thr), 2x2 warp grid, warp tile (BM/2)x(BN/2), BK=64, 3 stages.
// EPI 0: split-K partial store. EPI 1: out=C (+ pe broadcast), streaming stores.
template<int BM, int BN, int EPI, int OCC>
__global__ void __launch_bounds__(128, OCC)
k_mma(const __half* __restrict__ A, const __half* __restrict__ Bm,
      float* __restrict__ out, const float* __restrict__ pe,
      int M, int N, int K, int kcnt, size_t off2)
{
    constexpr int BK = 64, STAGES = 3, T = 128;
    constexpr int WM = BM / 2, WN = BN / 2;
    constexpr int MT = WM / 16, NT = WN / 8;     // MMA tiles per warp
    constexpr int ABYTES = BM * BK * 2;
    constexpr int BBYTES = BN * BK * 2;

    extern __shared__ char smem[];
    const uint32_t smA = (uint32_t)__cvta_generic_to_shared(smem);
    const uint32_t smB = smA + STAGES * ABYTES;

    const int t = threadIdx.x, lane = t & 31, warp = t >> 5;
    const int wm = warp >> 1, wn = warp & 1;      // 2x2 warps
    const int m0 = blockIdx.y * BM, n0 = blockIdx.x * BN;
    int k0 = 0;
    if (EPI == 0) { k0 = blockIdx.z * kcnt; out += (size_t)blockIdx.z * M * N; }

    // ldmatrix addressing (b16, 128B rows, SW128)
    const uint32_t xorv = (uint32_t)(lane & 7) * 16u;
    uint32_t aoff[MT], boff[NT / 2], acx[4], bcx[4];
    #pragma unroll
    for (int mt = 0; mt < MT; mt++)
        aoff[mt] = (uint32_t)((wm * WM + mt * 16 + (lane & 15)) * 128);
    #pragma unroll
    for (int p = 0; p < NT / 2; p++)
        boff[p] = (uint32_t)((wn * WN + p * 16 + (lane & 7) + ((lane & 16) >> 1)) * 128);
    #pragma unroll
    for (int ks = 0; ks < 4; ks++) {
        acx[ks] = ((uint32_t)(ks * 32) + (uint32_t)(lane & 16)) ^ xorv;
        bcx[ks] = ((uint32_t)(ks * 32) + (uint32_t)((lane & 8) << 1)) ^ xorv;
    }

    float acc[MT][NT][4];
    #pragma unroll
    for (int i = 0; i < MT; i++)
        #pragma unroll
        for (int j = 0; j < NT; j++)
            #pragma unroll
            for (int q = 0; q < 4; q++) acc[i][j][q] = 0.f;

    auto load_tile = [&](int stage, int kt) {
        const int kk = k0 + kt * BK;
        #pragma unroll
        for (int f = t; f < BM * 8; f += T) {
            const int r = f >> 3, c = f & 7;
            cp16(smA + (uint32_t)stage * ABYTES + SW128((uint32_t)(r * 128 + c * 16)),
                 A + (size_t)(m0 + r) * K + kk + c * 8);
        }
        #pragma unroll
        for (int f = t; f < BN * 8; f += T) {
            const int r = f >> 3, c = f & 7;
            cp16(smB + (uint32_t)stage * BBYTES + SW128((uint32_t)(r * 128 + c * 16)),
                 Bm + (size_t)(n0 + r) * K + kk + c * 8);
        }
        asm volatile("cp.async.commit_group;" ::: "memory");
    };

    const int KT = kcnt / BK;
    #pragma unroll
    for (int s = 0; s < STAGES - 1; s++) load_tile(s, s);

    #pragma unroll 1
    for (int kt = 0; kt < KT; kt++) {
        const int st = kt % STAGES;
        asm volatile("cp.async.wait_group %0;" :: "n"(STAGES - 2));
        __syncthreads();
        if (kt + STAGES - 1 < KT)
            load_tile((kt + STAGES - 1) % STAGES, kt + STAGES - 1);
        else
            asm volatile("cp.async.commit_group;" ::: "memory");

        const uint32_t aB = smA + (uint32_t)st * ABYTES;
        const uint32_t bB = smB + (uint32_t)st * BBYTES;
        #pragma unroll
        for (int ks = 0; ks < 4; ks++) {
            uint32_t a[MT][4], b[NT][2];
            #pragma unroll
            for (int mt = 0; mt < MT; mt++)
                LDSM4(a[mt][0], a[mt][1], a[mt][2], a[mt][3],
                      aB + aoff[mt] + acx[ks]);
            #pragma unroll
            for (int p = 0; p < NT / 2; p++)
                LDSM4(b[2 * p][0], b[2 * p][1], b[2 * p + 1][0], b[2 * p + 1][1],
                      bB + boff[p] + bcx[ks]);
            #pragma unroll
            for (int mt = 0; mt < MT; mt++)
                #pragma unroll
                for (int nt = 0; nt < NT; nt++)
                    MMA16(acc[mt][nt], a[mt], b[nt][0], b[nt][1]);
        }
    }

    // epilogue
    #pragma unroll
    for (int mt = 0; mt < MT; mt++) {
        const int r = m0 + wm * WM + mt * 16 + (lane >> 2);
        float pv0 = 0.f, pv1 = 0.f;
        if (EPI == 1) { pv0 = pe[r]; pv1 = pe[r + 8]; }
        #pragma unroll
        for (int nt = 0; nt < NT; nt++) {
            const int c = n0 + wn * WN + nt * 8 + 2 * (lane & 3);
            if (EPI == 0) {
                *(float2*)(out + (size_t)r * N + c) =
                    make_float2(acc[mt][nt][0], acc[mt][nt][1]);
                *(float2*)(out + (size_t)(r + 8) * N + c) =
                    make_float2(acc[mt][nt][2], acc[mt][nt][3]);
            } else {
                __stcs((float2*)(out + (size_t)r * N + c),
                       make_float2(acc[mt][nt][0], acc[mt][nt][1]));
                __stcs((float2*)(out + (size_t)(r + 8) * N + c),
                       make_float2(acc[mt][nt][2], acc[mt][nt][3]));
                __stcs((float2*)(out + off2 + (size_t)r * N + c), make_float2(pv0, pv0));
                __stcs((float2*)(out + off2 + (size_t)(r + 8) * N + c), make_float2(pv1, pv1));
            }
        }
    }
}

// ---------------- launch ----------------
extern "C" void kernel_launch(void* const* d_in, const int* in_sizes, int n_in,
                              void* d_out, int out_size)
{
    const float* vf    = (const float*)d_in[0];
    const float* pwfs  = (const float*)d_in[1];
    const float* nwfs  = (const float*)d_in[2];
    const float* gamma = (const float*)d_in[3];
    const float* beta  = (const float*)d_in[4];
    const float* W     = (const float*)d_in[5];
    const float* bias  = (const float*)d_in[6];
    float* out = (float*)d_out;

    __half *vfn_p, *emb_p, *nwn_p, *wr_p;
    float *pe_p, *part_p;
    cudaGetSymbolAddress((void**)&vfn_p,  g_vfn);
    cudaGetSymbolAddress((void**)&emb_p,  g_emb);
    cudaGetSymbolAddress((void**)&nwn_p,  g_nwn);
    cudaGetSymbolAddress((void**)&pe_p,   g_pe);
    cudaGetSymbolAddress((void**)&wr_p,   g_wr);
    cudaGetSymbolAddress((void**)&part_p, g_part);

    // 1: BN partial stats
    k_stats<<<512, 256>>>(vf);
    // 2: BN finalize
    k_stats_final<<<D_ / 256, 256>>>(gamma, beta);
    // 3: mega pass — BN apply + p_e | W->fp16 | nwn rownorm
    k_mega<<<2048 + 1024 + 4096, 256>>>(vf, pwfs, (const float4*)W, wr_p,
                                        (const float4*)nwfs, nwn_p);

    // 4: GEMM1 64x64 tiles, split-K=4 -> 1024 tiles, occ 4 (R12-measured best: 28.6us)
    constexpr int SM1 = 3 * (64 + 64) * 64 * 2;       // 48 KB
    cudaFuncSetAttribute(k_mma<64, 64, 0, 4>,
                         cudaFuncAttributeMaxDynamicSharedMemorySize, SM1);
    k_mma<64, 64, 0, 4><<<dim3(E_ / 64, B_ / 64, 4), 128, SM1>>>(
        vfn_p, wr_p, part_p, nullptr, B_, E_, D_, D_ / 4, 0);

    // 5: reduce 4 partials + bias + relu + rownorm -> fp16 emb
    k_fuse_emb<<<B_, 128>>>(bias);

    // 6: GEMM2 128x128 tiles, occ 2, 64x64 warp tiles (R10-measured best config)
    constexpr int SM2 = 3 * (128 + 128) * 64 * 2;     // 96 KB
    cudaFuncSetAttribute(k_mma<128, 128, 1, 2>,
                         cudaFuncAttributeMaxDynamicSharedMemorySize, SM2);
    const size_t off2 = (size_t)out_size / 2;
    k_mma<128, 128, 1, 2><<<dim3(NN_ / 128, B_ / 128), 128, SM2>>>(
        emb_p, nwn_p, out, pe_p, B_, NN_, E_, E_, off2);
}

// round 14
// speedup vs baseline: 1.0469x; 1.0343x over previous
#include <cuda_runtime.h>
#include <cuda_fp16.h>
#include <cstdint>

#define B_   2048
#define D_   4096
#define E_   512
#define NN_  8192
#define BN_EPS  1e-5f
#define COS_EPSF 1e-8f

// ---------------- scratch (__device__ globals; no allocations allowed) ----------------
__device__ float  g_psum[32][D_];
__device__ float  g_psq [32][D_];
__device__ float  g_scale[D_];
__device__ float  g_shift[D_];
__device__ __half g_vfn[B_ * D_];       // 17 MB (fp16 BN output)
__device__ float  g_pe [B_];
__device__ __half g_emb[B_ * E_];       // 2 MB (normalized, fp16)
__device__ __half g_nwn[NN_ * E_];      // 8 MB (normalized, fp16)
__device__ __half g_wr [E_ * D_];       // 4 MB (fp16 W)
__device__ float  g_part[4][B_ * E_];   // 16 MB split-K partials (fp32)

// ---------------- helpers ----------------
__device__ __forceinline__ void cp16(uint32_t dst, const void* src) {
    asm volatile("cp.async.cg.shared.global [%0], [%1], 16;" :: "r"(dst), "l"(src));
}
#define SW128(o) ((o) ^ (((o) >> 3) & 0x70))

#define LDSM4(r0, r1, r2, r3, a) \
    asm volatile("ldmatrix.sync.aligned.m8n8.x4.shared.b16 {%0,%1,%2,%3}, [%4];" \
                 : "=r"(r0), "=r"(r1), "=r"(r2), "=r"(r3) : "r"(a))

#define MMA16(d, av, b0v, b1v) \
    asm volatile("mma.sync.aligned.m16n8k16.row.col.f32.f16.f16.f32 " \
                 "{%0,%1,%2,%3}, {%4,%5,%6,%7}, {%8,%9}, {%0,%1,%2,%3};" \
                 : "+f"((d)[0]), "+f"((d)[1]), "+f"((d)[2]), "+f"((d)[3]) \
                 : "r"((av)[0]), "r"((av)[1]), "r"((av)[2]), "r"((av)[3]), \
                   "r"(b0v), "r"(b1v))

__device__ __forceinline__ uint32_t h2pack(float a, float b) {
    const __half2 h = __floats2half2_rn(a, b);
    return *reinterpret_cast<const uint32_t*>(&h);
}

// ------- prep pass: BN stats [0,512) | W->fp16 [512,1536) | nwn norm [1536,5632) -----
// stats blocks are latency-bound; W/nwn blocks are streaming — co-residency overlaps.
__global__ void __launch_bounds__(256) k_prep(const float* __restrict__ vf,
                                              const float4* __restrict__ W,
                                              __half* __restrict__ Wr,
                                              const float4* __restrict__ nwfs,
                                              __half* __restrict__ nwn) {
    const int t = threadIdx.x;
    if (blockIdx.x < 512) {
        const int bid = blockIdx.x;
        const int c = (bid & 15) * 256 + t;
        const int chunk = bid >> 4;              // 0..31
        const int r0 = chunk * 64;
        float s = 0.f, q = 0.f;
        #pragma unroll 4
        for (int r = 0; r < 64; r++) {
            float v = vf[(size_t)(r0 + r) * D_ + c];
            s += v; q += v * v;
        }
        g_psum[chunk][c] = s;
        g_psq [chunk][c] = q;
    } else if (blockIdx.x < 1536) {
        const int gl = (blockIdx.x - 512) * 256 + t;   // 8 floats per thread
        const float4 v0 = __ldcs(&W[gl * 2]), v1 = __ldcs(&W[gl * 2 + 1]);
        uint4 o;
        o.x = h2pack(v0.x, v0.y); o.y = h2pack(v0.z, v0.w);
        o.z = h2pack(v1.x, v1.y); o.w = h2pack(v1.z, v1.w);
        ((uint4*)Wr)[gl] = o;
    } else {
        const int seg = blockIdx.x - 1536;             // 0..4095, 2 rows each
        const int half = t >> 7;
        const int tt = t & 127;
        const int row = seg * 2 + half;
        const float4 v = __ldcs(&nwfs[(size_t)row * 128 + tt]);
        float s = v.x * v.x + v.y * v.y + v.z * v.z + v.w * v.w;
        #pragma unroll
        for (int o = 16; o; o >>= 1) s += __shfl_down_sync(0xffffffffu, s, o);
        __shared__ float ss[8];
        const int w = t >> 5;
        if ((t & 31) == 0) ss[w] = s;
        __syncthreads();
        const int b0 = half * 4;
        const float tot = ss[b0] + ss[b0 + 1] + ss[b0 + 2] + ss[b0 + 3];
        const float inv = 1.0f / fmaxf(sqrtf(tot), COS_EPSF);
        uint2 o;
        o.x = h2pack(v.x * inv, v.y * inv);
        o.y = h2pack(v.z * inv, v.w * inv);
        ((uint2*)(nwn + (size_t)row * E_))[tt] = o;
    }
}

__global__ void k_stats_final(const float* __restrict__ gamma,
                              const float* __restrict__ beta) {
    const int c = blockIdx.x * 256 + threadIdx.x;
    float s = 0.f, q = 0.f;
    #pragma unroll
    for (int i = 0; i < 32; i++) { s += g_psum[i][c]; q += g_psq[i][c]; }
    const float mean = s * (1.0f / B_);
    const float var  = q * (1.0f / B_) - mean * mean;
    const float sc   = gamma[c] * rsqrtf(var + BN_EPS);
    g_scale[c] = sc;
    g_shift[c] = beta[c] - mean * sc;
}

// ---------------- fused BN apply + p_e (row cosine); stores fp16 vfn -----------------
__global__ void __launch_bounds__(256) k_bn_pe(const float* __restrict__ vf,
                                               const float* __restrict__ p) {
    const int row = blockIdx.x;
    const int t = threadIdx.x;
    const float4* v4  = (const float4*)(vf + (size_t)row * D_);
    const float4* p4  = (const float4*)(p  + (size_t)row * D_);
    const float4* sc4 = (const float4*)g_scale;
    const float4* sh4 = (const float4*)g_shift;
    uint2* o2 = (uint2*)(g_vfn + (size_t)row * D_);

    float dot = 0.f, nv = 0.f, np = 0.f;
    #pragma unroll
    for (int u = 0; u < 2; u++) {
        const int i0 = t + u * 512;
        const float4 va = __ldcs(&v4[i0]);
        const float4 vb = __ldcs(&v4[i0 + 256]);
        const float4 pa = __ldcs(&p4[i0]);
        const float4 pb = __ldcs(&p4[i0 + 256]);
        const float4 sa = sc4[i0], sb = sc4[i0 + 256];
        const float4 ha = sh4[i0], hb = sh4[i0 + 256];
        float4 xa, xb;
        xa.x = va.x * sa.x + ha.x; xa.y = va.y * sa.y + ha.y;
        xa.z = va.z * sa.z + ha.z; xa.w = va.w * sa.w + ha.w;
        xb.x = vb.x * sb.x + hb.x; xb.y = vb.y * sb.y + hb.y;
        xb.z = vb.z * sb.z + hb.z; xb.w = vb.w * sb.w + hb.w;
        uint2 ra, rb;
        ra.x = h2pack(xa.x, xa.y); ra.y = h2pack(xa.z, xa.w);
        rb.x = h2pack(xb.x, xb.y); rb.y = h2pack(xb.z, xb.w);
        o2[i0] = ra;
        o2[i0 + 256] = rb;
        dot += xa.x * pa.x + xa.y * pa.y + xa.z * pa.z + xa.w * pa.w;
        dot += xb.x * pb.x + xb.y * pb.y + xb.z * pb.z + xb.w * pb.w;
        nv  += xa.x * xa.x + xa.y * xa.y + xa.z * xa.z + xa.w * xa.w;
        nv  += xb.x * xb.x + xb.y * xb.y + xb.z * xb.z + xb.w * xb.w;
        np  += pa.x * pa.x + pa.y * pa.y + pa.z * pa.z + pa.w * pa.w;
        np  += pb.x * pb.x + pb.y * pb.y + pb.z * pb.z + pb.w * pb.w;
    }
    #pragma unroll
    for (int o = 16; o; o >>= 1) {
        dot += __shfl_down_sync(0xffffffffu, dot, o);
        nv  += __shfl_down_sync(0xffffffffu, nv,  o);
        np  += __shfl_down_sync(0xffffffffu, np,  o);
    }
    __shared__ float sd[8], sn[8], sp[8];
    const int lane = t & 31, w = t >> 5;
    if (lane == 0) { sd[w] = dot; sn[w] = nv; sp[w] = np; }
    __syncthreads();
    if (t == 0) {
        float Dv = 0.f, NV = 0.f, NP = 0.f;
        #pragma unroll
        for (int i = 0; i < 8; i++) { Dv += sd[i]; NV += sn[i]; NP += sp[i]; }
        g_pe[row] = Dv / (fmaxf(sqrtf(NV), COS_EPSF) * fmaxf(sqrtf(NP), COS_EPSF));
    }
}

// ---------------- split-K(4) reduce + bias + relu + rownorm -> fp16 g_emb ------------
__global__ void k_fuse_emb(const float* __restrict__ bias) {
    const int row = blockIdx.x;
    const int t = threadIdx.x;
    float4 s = make_float4(0.f, 0.f, 0.f, 0.f);
    #pragma unroll
    for (int p = 0; p < 4; p++) {
        const float4 v = *(const float4*)(&g_part[p][(size_t)row * E_ + t * 4]);
        s.x += v.x; s.y += v.y; s.z += v.z; s.w += v.w;
    }
    const float4 bq = ((const float4*)bias)[t];
    s.x = fmaxf(s.x + bq.x, 0.f);
    s.y = fmaxf(s.y + bq.y, 0.f);
    s.z = fmaxf(s.z + bq.z, 0.f);
    s.w = fmaxf(s.w + bq.w, 0.f);
    float nrm = s.x * s.x + s.y * s.y + s.z * s.z + s.w * s.w;
    #pragma unroll
    for (int o = 16; o; o >>= 1) nrm += __shfl_down_sync(0xffffffffu, nrm, o);
    __shared__ float ss[4];
    if ((t & 31) == 0) ss[t >> 5] = nrm;
    __syncthreads();
    const float tot = ss[0] + ss[1] + ss[2] + ss[3];
    const float inv = 1.0f / fmaxf(sqrtf(tot), COS_EPSF);
    uint2 o;
    o.x = h2pack(s.x * inv, s.y * inv);
    o.y = h2pack(s.z * inv, s.w * inv);
    ((uint2*)(g_emb + (size_t)row * E_))[t] = o;
}

// ---------------- fp16 mma.sync GEMM, templated tile -------------------------------
// 4 warps (128 thr), 2x2 warp grid, warp tile (BM/2)x(BN/2), BK=64, 3 stages.
// EPI 0: split-K partial store. EPI 1: out=C (+ pe broadcast), streaming stores.
template<int BM, int BN, int EPI, int OCC>
__global__ void __launch_bounds__(128, OCC)
k_mma(const __half* __restrict__ A, const __half* __restrict__ Bm,
      float* __restrict__ out, const float* __restrict__ pe,
      int M, int N, int K, int kcnt, size_t off2)
{
    constexpr int BK = 64, STAGES = 3, T = 128;
    constexpr int WM = BM / 2, WN = BN / 2;
    constexpr int MT = WM / 16, NT = WN / 8;     // MMA tiles per warp
    constexpr int ABYTES = BM * BK * 2;
    constexpr int BBYTES = BN * BK * 2;

    extern __shared__ char smem[];
    const uint32_t smA = (uint32_t)__cvta_generic_to_shared(smem);
    const uint32_t smB = smA + STAGES * ABYTES;

    const int t = threadIdx.x, lane = t & 31, warp = t >> 5;
    const int wm = warp >> 1, wn = warp & 1;      // 2x2 warps
    const int m0 = blockIdx.y * BM, n0 = blockIdx.x * BN;
    int k0 = 0;
    if (EPI == 0) { k0 = blockIdx.z * kcnt; out += (size_t)blockIdx.z * M * N; }

    // ldmatrix addressing (b16, 128B rows, SW128)
    const uint32_t xorv = (uint32_t)(lane & 7) * 16u;
    uint32_t aoff[MT], boff[NT / 2], acx[4], bcx[4];
    #pragma unroll
    for (int mt = 0; mt < MT; mt++)
        aoff[mt] = (uint32_t)((wm * WM + mt * 16 + (lane & 15)) * 128);
    #pragma unroll
    for (int p = 0; p < NT / 2; p++)
        boff[p] = (uint32_t)((wn * WN + p * 16 + (lane & 7) + ((lane & 16) >> 1)) * 128);
    #pragma unroll
    for (int ks = 0; ks < 4; ks++) {
        acx[ks] = ((uint32_t)(ks * 32) + (uint32_t)(lane & 16)) ^ xorv;
        bcx[ks] = ((uint32_t)(ks * 32) + (uint32_t)((lane & 8) << 1)) ^ xorv;
    }

    float acc[MT][NT][4];
    #pragma unroll
    for (int i = 0; i < MT; i++)
        #pragma unroll
        for (int j = 0; j < NT; j++)
            #pragma unroll
            for (int q = 0; q < 4; q++) acc[i][j][q] = 0.f;

    auto load_tile = [&](int stage, int kt) {
        const int kk = k0 + kt * BK;
        #pragma unroll
        for (int f = t; f < BM * 8; f += T) {
            const int r = f >> 3, c = f & 7;
            cp16(smA + (uint32_t)stage * ABYTES + SW128((uint32_t)(r * 128 + c * 16)),
                 A + (size_t)(m0 + r) * K + kk + c * 8);
        }
        #pragma unroll
        for (int f = t; f < BN * 8; f += T) {
            const int r = f >> 3, c = f & 7;
            cp16(smB + (uint32_t)stage * BBYTES + SW128((uint32_t)(r * 128 + c * 16)),
                 Bm + (size_t)(n0 + r) * K + kk + c * 8);
        }
        asm volatile("cp.async.commit_group;" ::: "memory");
    };

    const int KT = kcnt / BK;
    #pragma unroll
    for (int s = 0; s < STAGES - 1; s++) load_tile(s, s);

    #pragma unroll 1
    for (int kt = 0; kt < KT; kt++) {
        const int st = kt % STAGES;
        asm volatile("cp.async.wait_group %0;" :: "n"(STAGES - 2));
        __syncthreads();
        if (kt + STAGES - 1 < KT)
            load_tile((kt + STAGES - 1) % STAGES, kt + STAGES - 1);
        else
            asm volatile("cp.async.commit_group;" ::: "memory");

        const uint32_t aB = smA + (uint32_t)st * ABYTES;
        const uint32_t bB = smB + (uint32_t)st * BBYTES;
        #pragma unroll
        for (int ks = 0; ks < 4; ks++) {
            uint32_t a[MT][4], b[NT][2];
            #pragma unroll
            for (int mt = 0; mt < MT; mt++)
                LDSM4(a[mt][0], a[mt][1], a[mt][2], a[mt][3],
                      aB + aoff[mt] + acx[ks]);
            #pragma unroll
            for (int p = 0; p < NT / 2; p++)
                LDSM4(b[2 * p][0], b[2 * p][1], b[2 * p + 1][0], b[2 * p + 1][1],
                      bB + boff[p] + bcx[ks]);
            #pragma unroll
            for (int mt = 0; mt < MT; mt++)
                #pragma unroll
                for (int nt = 0; nt < NT; nt++)
                    MMA16(acc[mt][nt], a[mt], b[nt][0], b[nt][1]);
        }
    }

    // epilogue
    #pragma unroll
    for (int mt = 0; mt < MT; mt++) {
        const int r = m0 + wm * WM + mt * 16 + (lane >> 2);
        float pv0 = 0.f, pv1 = 0.f;
        if (EPI == 1) { pv0 = pe[r]; pv1 = pe[r + 8]; }
        #pragma unroll
        for (int nt = 0; nt < NT; nt++) {
            const int c = n0 + wn * WN + nt * 8 + 2 * (lane & 3);
            if (EPI == 0) {
                *(float2*)(out + (size_t)r * N + c) =
                    make_float2(acc[mt][nt][0], acc[mt][nt][1]);
                *(float2*)(out + (size_t)(r + 8) * N + c) =
                    make_float2(acc[mt][nt][2], acc[mt][nt][3]);
            } else {
                __stcs((float2*)(out + (size_t)r * N + c),
                       make_float2(acc[mt][nt][0], acc[mt][nt][1]));
                __stcs((float2*)(out + (size_t)(r + 8) * N + c),
                       make_float2(acc[mt][nt][2], acc[mt][nt][3]));
                __stcs((float2*)(out + off2 + (size_t)r * N + c), make_float2(pv0, pv0));
                __stcs((float2*)(out + off2 + (size_t)(r + 8) * N + c), make_float2(pv1, pv1));
            }
        }
    }
}

// ---------------- launch ----------------
extern "C" void kernel_launch(void* const* d_in, const int* in_sizes, int n_in,
                              void* d_out, int out_size)
{
    const float* vf    = (const float*)d_in[0];
    const float* pwfs  = (const float*)d_in[1];
    const float* nwfs  = (const float*)d_in[2];
    const float* gamma = (const float*)d_in[3];
    const float* beta  = (const float*)d_in[4];
    const float* W     = (const float*)d_in[5];
    const float* bias  = (const float*)d_in[6];
    float* out = (float*)d_out;

    __half *vfn_p, *emb_p, *nwn_p, *wr_p;
    float *pe_p, *part_p;
    cudaGetSymbolAddress((void**)&vfn_p,  g_vfn);
    cudaGetSymbolAddress((void**)&emb_p,  g_emb);
    cudaGetSymbolAddress((void**)&nwn_p,  g_nwn);
    cudaGetSymbolAddress((void**)&pe_p,   g_pe);
    cudaGetSymbolAddress((void**)&wr_p,   g_wr);
    cudaGetSymbolAddress((void**)&part_p, g_part);

    // 1: prep — BN stats (latency-bound) co-resident with W->fp16 + nwn (streaming)
    k_prep<<<512 + 1024 + 4096, 256>>>(vf, (const float4*)W, wr_p,
                                       (const float4*)nwfs, nwn_p);
    // 2: BN finalize
    k_stats_final<<<D_ / 256, 256>>>(gamma, beta);
    // 3: BN apply (fp16 store) + p_e
    k_bn_pe<<<B_, 256>>>(vf, pwfs);

    // 4: GEMM1 64x64 tiles, split-K=4 -> 1024 tiles, occ 4 (measured best: 28.6us)
    constexpr int SM1 = 3 * (64 + 64) * 64 * 2;       // 48 KB
    cudaFuncSetAttribute(k_mma<64, 64, 0, 4>,
                         cudaFuncAttributeMaxDynamicSharedMemorySize, SM1);
    k_mma<64, 64, 0, 4><<<dim3(E_ / 64, B_ / 64, 4), 128, SM1>>>(
        vfn_p, wr_p, part_p, nullptr, B_, E_, D_, D_ / 4, 0);

    // 5: reduce 4 partials + bias + relu + rownorm -> fp16 emb
    k_fuse_emb<<<B_, 128>>>(bias);

    // 6: GEMM2 128x128 tiles, occ 2, 64x64 warp tiles (measured best config)
    constexpr int SM2 = 3 * (128 + 128) * 64 * 2;     // 96 KB
    cudaFuncSetAttribute(k_mma<128, 128, 1, 2>,
                         cudaFuncAttributeMaxDynamicSharedMemorySize, SM2);
    const size_t off2 = (size_t)out_size / 2;
    k_mma<128, 128, 1, 2><<<dim3(NN_ / 128, B_ / 128), 128, SM2>>>(
        emb_p, nwn_p, out, pe_p, B_, NN_, E_, E_, off2);
}

// round 16
// speedup vs baseline: 1.0516x; 1.0046x over previous
#include <cuda_runtime.h>
#include <cuda_fp16.h>
#include <cstdint>

#define B_   2048
#define D_   4096
#define E_   512
#define NN_  8192
#define BN_EPS  1e-5f
#define COS_EPSF 1e-8f

// ---------------- scratch (__device__ globals; no allocations allowed) ----------------
__device__ float  g_psum[32][D_];
__device__ float  g_psq [32][D_];
__device__ float  g_scale[D_];
__device__ float  g_shift[D_];
__device__ __half g_vfn[B_ * D_];       // 17 MB (fp16 BN output)
__device__ float  g_pe [B_];
__device__ __half g_emb[B_ * E_];       // 2 MB (normalized, fp16)
__device__ __half g_nwn[NN_ * E_];      // 8 MB (normalized, fp16)
__device__ __half g_wr [E_ * D_];       // 4 MB (fp16 W)
__device__ float  g_part[4][B_ * E_];   // 16 MB split-K partials (fp32)

// ---------------- helpers ----------------
__device__ __forceinline__ void cp16(uint32_t dst, const void* src) {
    asm volatile("cp.async.cg.shared.global [%0], [%1], 16;" :: "r"(dst), "l"(src));
}
#define SW128(o) ((o) ^ (((o) >> 3) & 0x70))

#define LDSM4(r0, r1, r2, r3, a) \
    asm volatile("ldmatrix.sync.aligned.m8n8.x4.shared.b16 {%0,%1,%2,%3}, [%4];" \
                 : "=r"(r0), "=r"(r1), "=r"(r2), "=r"(r3) : "r"(a))

#define MMA16(d, av, b0v, b1v) \
    asm volatile("mma.sync.aligned.m16n8k16.row.col.f32.f16.f16.f32 " \
                 "{%0,%1,%2,%3}, {%4,%5,%6,%7}, {%8,%9}, {%0,%1,%2,%3};" \
                 : "+f"((d)[0]), "+f"((d)[1]), "+f"((d)[2]), "+f"((d)[3]) \
                 : "r"((av)[0]), "r"((av)[1]), "r"((av)[2]), "r"((av)[3]), \
                   "r"(b0v), "r"(b1v))

__device__ __forceinline__ uint32_t h2pack(float a, float b) {
    const __half2 h = __floats2half2_rn(a, b);
    return *reinterpret_cast<const uint32_t*>(&h);
}

// ------- prep pass: BN stats [0,512) | W->fp16 [512,1536) | nwn norm [1536,5632) -----
__global__ void __launch_bounds__(256) k_prep(const float* __restrict__ vf,
                                              const float4* __restrict__ W,
                                              __half* __restrict__ Wr,
                                              const float4* __restrict__ nwfs,
                                              __half* __restrict__ nwn) {
    const int t = threadIdx.x;
    if (blockIdx.x < 512) {
        const int bid = blockIdx.x;
        const int c = (bid & 15) * 256 + t;
        const int chunk = bid >> 4;              // 0..31
        const int r0 = chunk * 64;
        float s = 0.f, q = 0.f;
        #pragma unroll 4
        for (int r = 0; r < 64; r++) {
            float v = vf[(size_t)(r0 + r) * D_ + c];
            s += v; q += v * v;
        }
        g_psum[chunk][c] = s;
        g_psq [chunk][c] = q;
    } else if (blockIdx.x < 1536) {
        const int gl = (blockIdx.x - 512) * 256 + t;   // 8 floats per thread
        const float4 v0 = __ldcs(&W[gl * 2]), v1 = __ldcs(&W[gl * 2 + 1]);
        uint4 o;
        o.x = h2pack(v0.x, v0.y); o.y = h2pack(v0.z, v0.w);
        o.z = h2pack(v1.x, v1.y); o.w = h2pack(v1.z, v1.w);
        ((uint4*)Wr)[gl] = o;
    } else {
        const int seg = blockIdx.x - 1536;             // 0..4095, 2 rows each
        const int half = t >> 7;
        const int tt = t & 127;
        const int row = seg * 2 + half;
        const float4 v = __ldcs(&nwfs[(size_t)row * 128 + tt]);
        float s = v.x * v.x + v.y * v.y + v.z * v.z + v.w * v.w;
        #pragma unroll
        for (int o = 16; o; o >>= 1) s += __shfl_down_sync(0xffffffffu, s, o);
        __shared__ float ss[8];
        const int w = t >> 5;
        if ((t & 31) == 0) ss[w] = s;
        __syncthreads();
        const int b0 = half * 4;
        const float tot = ss[b0] + ss[b0 + 1] + ss[b0 + 2] + ss[b0 + 3];
        const float inv = 1.0f / fmaxf(sqrtf(tot), COS_EPSF);
        uint2 o;
        o.x = h2pack(v.x * inv, v.y * inv);
        o.y = h2pack(v.z * inv, v.w * inv);
        ((uint2*)(nwn + (size_t)row * E_))[tt] = o;
    }
}

__global__ void k_stats_final(const float* __restrict__ gamma,
                              const float* __restrict__ beta) {
    const int c = blockIdx.x * 256 + threadIdx.x;
    float s = 0.f, q = 0.f;
    #pragma unroll
    for (int i = 0; i < 32; i++) { s += g_psum[i][c]; q += g_psq[i][c]; }
    const float mean = s * (1.0f / B_);
    const float var  = q * (1.0f / B_) - mean * mean;
    const float sc   = gamma[c] * rsqrtf(var + BN_EPS);
    g_scale[c] = sc;
    g_shift[c] = beta[c] - mean * sc;
}

// ---------------- fused BN apply + p_e (row cosine); stores fp16 vfn -----------------
__global__ void __launch_bounds__(256) k_bn_pe(const float* __restrict__ vf,
                                               const float* __restrict__ p) {
    const int row = blockIdx.x;
    const int t = threadIdx.x;
    const float4* v4  = (const float4*)(vf + (size_t)row * D_);
    const float4* p4  = (const float4*)(p  + (size_t)row * D_);
    const float4* sc4 = (const float4*)g_scale;
    const float4* sh4 = (const float4*)g_shift;
    uint2* o2 = (uint2*)(g_vfn + (size_t)row * D_);

    // hoist all main-stream loads (MLP 16)
    float4 va[4], pa[4];
    #pragma unroll
    for (int u = 0; u < 4; u++) va[u] = __ldcs(&v4[t + u * 256]);
    #pragma unroll
    for (int u = 0; u < 4; u++) pa[u] = __ldcs(&p4[t + u * 256]);

    float dot = 0.f, nv = 0.f, np = 0.f;
    #pragma unroll
    for (int u = 0; u < 4; u++) {
        const int i0 = t + u * 256;
        const float4 sa = sc4[i0], ha = sh4[i0];
        float4 x;
        x.x = va[u].x * sa.x + ha.x; x.y = va[u].y * sa.y + ha.y;
        x.z = va[u].z * sa.z + ha.z; x.w = va[u].w * sa.w + ha.w;
        uint2 r;
        r.x = h2pack(x.x, x.y); r.y = h2pack(x.z, x.w);
        o2[i0] = r;
        dot += x.x * pa[u].x + x.y * pa[u].y + x.z * pa[u].z + x.w * pa[u].w;
        nv  += x.x * x.x + x.y * x.y + x.z * x.z + x.w * x.w;
        np  += pa[u].x * pa[u].x + pa[u].y * pa[u].y
             + pa[u].z * pa[u].z + pa[u].w * pa[u].w;
    }
    #pragma unroll
    for (int o = 16; o; o >>= 1) {
        dot += __shfl_down_sync(0xffffffffu, dot, o);
        nv  += __shfl_down_sync(0xffffffffu, nv,  o);
        np  += __shfl_down_sync(0xffffffffu, np,  o);
    }
    __shared__ float sd[8], sn[8], sp[8];
    const int lane = t & 31, w = t >> 5;
    if (lane == 0) { sd[w] = dot; sn[w] = nv; sp[w] = np; }
    __syncthreads();
    if (t == 0) {
        float Dv = 0.f, NV = 0.f, NP = 0.f;
        #pragma unroll
        for (int i = 0; i < 8; i++) { Dv += sd[i]; NV += sn[i]; NP += sp[i]; }
        g_pe[row] = Dv / (fmaxf(sqrtf(NV), COS_EPSF) * fmaxf(sqrtf(NP), COS_EPSF));
    }
}

// ------ split-K(4) reduce + bias + relu + rownorm -> fp16 g_emb (warp-per-row) -------
// 32 threads own one row of 512: 4 float4/thread/partial, shfl-only reduce.
__global__ void __launch_bounds__(256) k_fuse_emb(const float* __restrict__ bias) {
    const int t = threadIdx.x;
    const int lane = t & 31;
    const int row = blockIdx.x * 8 + (t >> 5);     // 8 rows per block
    const size_t base = (size_t)row * E_;

    // 16 independent float4 loads (4 partials x 4 chunks) for max MLP; L2-resident
    float4 v[4][4];
    #pragma unroll
    for (int p = 0; p < 4; p++) {
        const float4* src = (const float4*)(g_part[p] + base);
        #pragma unroll
        for (int j = 0; j < 4; j++)
            v[p][j] = __ldcs(&src[lane + j * 32]);
    }
    float4 s[4];
    #pragma unroll
    for (int j = 0; j < 4; j++) {
        s[j].x = v[0][j].x + v[1][j].x + v[2][j].x + v[3][j].x;
        s[j].y = v[0][j].y + v[1][j].y + v[2][j].y + v[3][j].y;
        s[j].z = v[0][j].z + v[1][j].z + v[2][j].z + v[3][j].z;
        s[j].w = v[0][j].w + v[1][j].w + v[2][j].w + v[3][j].w;
    }
    float nrm = 0.f;
    #pragma unroll
    for (int j = 0; j < 4; j++) {
        const float4 bq = ((const float4*)bias)[lane + j * 32];
        s[j].x = fmaxf(s[j].x + bq.x, 0.f);
        s[j].y = fmaxf(s[j].y + bq.y, 0.f);
        s[j].z = fmaxf(s[j].z + bq.z, 0.f);
        s[j].w = fmaxf(s[j].w + bq.w, 0.f);
        nrm += s[j].x * s[j].x + s[j].y * s[j].y + s[j].z * s[j].z + s[j].w * s[j].w;
    }
    #pragma unroll
    for (int o = 16; o; o >>= 1) nrm += __shfl_xor_sync(0xffffffffu, nrm, o);
    const float inv = 1.0f / fmaxf(sqrtf(nrm), COS_EPSF);
    #pragma unroll
    for (int j = 0; j < 4; j++) {
        uint2 o;
        o.x = h2pack(s[j].x * inv, s[j].y * inv);
        o.y = h2pack(s[j].z * inv, s[j].w * inv);
        ((uint2*)(g_emb + base))[lane + j * 32] = o;
    }
}

// ---------------- fp16 mma.sync GEMM, templated tile -------------------------------
// 4 warps (128 thr), 2x2 warp grid, warp tile (BM/2)x(BN/2), BK=64, 3 stages.
// EPI 0: split-K partial store. EPI 1: out=C (+ pe broadcast), streaming stores.
template<int BM, int BN, int EPI, int OCC>
__global__ void __launch_bounds__(128, OCC)
k_mma(const __half* __restrict__ A, const __half* __restrict__ Bm,
      float* __restrict__ out, const float* __restrict__ pe,
      int M, int N, int K, int kcnt, size_t off2)
{
    constexpr int BK = 64, STAGES = 3, T = 128;
    constexpr int WM = BM / 2, WN = BN / 2;
    constexpr int MT = WM / 16, NT = WN / 8;
    constexpr int ABYTES = BM * BK * 2;
    constexpr int BBYTES = BN * BK * 2;

    extern __shared__ char smem[];
    const uint32_t smA = (uint32_t)__cvta_generic_to_shared(smem);
    const uint32_t smB = smA + STAGES * ABYTES;

    const int t = threadIdx.x, lane = t & 31, warp = t >> 5;
    const int wm = warp >> 1, wn = warp & 1;
    const int m0 = blockIdx.y * BM, n0 = blockIdx.x * BN;
    int k0 = 0;
    if (EPI == 0) { k0 = blockIdx.z * kcnt; out += (size_t)blockIdx.z * M * N; }

    const uint32_t xorv = (uint32_t)(lane & 7) * 16u;
    uint32_t aoff[MT], boff[NT / 2], acx[4], bcx[4];
    #pragma unroll
    for (int mt = 0; mt < MT; mt++)
        aoff[mt] = (uint32_t)((wm * WM + mt * 16 + (lane & 15)) * 128);
    #pragma unroll
    for (int p = 0; p < NT / 2; p++)
        boff[p] = (uint32_t)((wn * WN + p * 16 + (lane & 7) + ((lane & 16) >> 1)) * 128);
    #pragma unroll
    for (int ks = 0; ks < 4; ks++) {
        acx[ks] = ((uint32_t)(ks * 32) + (uint32_t)(lane & 16)) ^ xorv;
        bcx[ks] = ((uint32_t)(ks * 32) + (uint32_t)((lane & 8) << 1)) ^ xorv;
    }

    float acc[MT][NT][4];
    #pragma unroll
    for (int i = 0; i < MT; i++)
        #pragma unroll
        for (int j = 0; j < NT; j++)
            #pragma unroll
            for (int q = 0; q < 4; q++) acc[i][j][q] = 0.f;

    auto load_tile = [&](int stage, int kt) {
        const int kk = k0 + kt * BK;
        #pragma unroll
        for (int f = t; f < BM * 8; f += T) {
            const int r = f >> 3, c = f & 7;
            cp16(smA + (uint32_t)stage * ABYTES + SW128((uint32_t)(r * 128 + c * 16)),
                 A + (size_t)(m0 + r) * K + kk + c * 8);
        }
        #pragma unroll
        for (int f = t; f < BN * 8; f += T) {
            const int r = f >> 3, c = f & 7;
            cp16(smB + (uint32_t)stage * BBYTES + SW128((uint32_t)(r * 128 + c * 16)),
                 Bm + (size_t)(n0 + r) * K + kk + c * 8);
        }
        asm volatile("cp.async.commit_group;" ::: "memory");
    };

    const int KT = kcnt / BK;
    #pragma unroll
    for (int s = 0; s < STAGES - 1; s++) load_tile(s, s);

    #pragma unroll 1
    for (int kt = 0; kt < KT; kt++) {
        const int st = kt % STAGES;
        asm volatile("cp.async.wait_group %0;" :: "n"(STAGES - 2));
        __syncthreads();
        if (kt + STAGES - 1 < KT)
            load_tile((kt + STAGES - 1) % STAGES, kt + STAGES - 1);
        else
            asm volatile("cp.async.commit_group;" ::: "memory");

        const uint32_t aB = smA + (uint32_t)st * ABYTES;
        const uint32_t bB = smB + (uint32_t)st * BBYTES;
        #pragma unroll
        for (int ks = 0; ks < 4; ks++) {
            uint32_t a[MT][4], b[NT][2];
            #pragma unroll
            for (int mt = 0; mt < MT; mt++)
                LDSM4(a[mt][0], a[mt][1], a[mt][2], a[mt][3],
                      aB + aoff[mt] + acx[ks]);
            #pragma unroll
            for (int p = 0; p < NT / 2; p++)
                LDSM4(b[2 * p][0], b[2 * p][1], b[2 * p + 1][0], b[2 * p + 1][1],
                      bB + boff[p] + bcx[ks]);
            #pragma unroll
            for (int mt = 0; mt < MT; mt++)
                #pragma unroll
                for (int nt = 0; nt < NT; nt++)
                    MMA16(acc[mt][nt], a[mt], b[nt][0], b[nt][1]);
        }
    }

    // epilogue
    #pragma unroll
    for (int mt = 0; mt < MT; mt++) {
        const int r = m0 + wm * WM + mt * 16 + (lane >> 2);
        float pv0 = 0.f, pv1 = 0.f;
        if (EPI == 1) { pv0 = pe[r]; pv1 = pe[r + 8]; }
        #pragma unroll
        for (int nt = 0; nt < NT; nt++) {
            const int c = n0 + wn * WN + nt * 8 + 2 * (lane & 3);
            if (EPI == 0) {
                *(float2*)(out + (size_t)r * N + c) =
                    make_float2(acc[mt][nt][0], acc[mt][nt][1]);
                *(float2*)(out + (size_t)(r + 8) * N + c) =
                    make_float2(acc[mt][nt][2], acc[mt][nt][3]);
            } else {
                __stcs((float2*)(out + (size_t)r * N + c),
                       make_float2(acc[mt][nt][0], acc[mt][nt][1]));
                __stcs((float2*)(out + (size_t)(r + 8) * N + c),
                       make_float2(acc[mt][nt][2], acc[mt][nt][3]));
                __stcs((float2*)(out + off2 + (size_t)r * N + c), make_float2(pv0, pv0));
                __stcs((float2*)(out + off2 + (size_t)(r + 8) * N + c), make_float2(pv1, pv1));
            }
        }
    }
}

// ---------------- launch ----------------
extern "C" void kernel_launch(void* const* d_in, const int* in_sizes, int n_in,
                              void* d_out, int out_size)
{
    const float* vf    = (const float*)d_in[0];
    const float* pwfs  = (const float*)d_in[1];
    const float* nwfs  = (const float*)d_in[2];
    const float* gamma = (const float*)d_in[3];
    const float* beta  = (const float*)d_in[4];
    const float* W     = (const float*)d_in[5];
    const float* bias  = (const float*)d_in[6];
    float* out = (float*)d_out;

    __half *vfn_p, *emb_p, *nwn_p, *wr_p;
    float *pe_p, *part_p;
    cudaGetSymbolAddress((void**)&vfn_p,  g_vfn);
    cudaGetSymbolAddress((void**)&emb_p,  g_emb);
    cudaGetSymbolAddress((void**)&nwn_p,  g_nwn);
    cudaGetSymbolAddress((void**)&pe_p,   g_pe);
    cudaGetSymbolAddress((void**)&wr_p,   g_wr);
    cudaGetSymbolAddress((void**)&part_p, g_part);

    // 1: prep — BN stats co-resident with W->fp16 + nwn rownorm
    k_prep<<<512 + 1024 + 4096, 256>>>(vf, (const float4*)W, wr_p,
                                       (const float4*)nwfs, nwn_p);
    // 2: BN finalize
    k_stats_final<<<D_ / 256, 256>>>(gamma, beta);
    // 3: BN apply (fp16 store) + p_e
    k_bn_pe<<<B_, 256>>>(vf, pwfs);

    // 4: GEMM1 64x64 tiles, split-K=4 -> 1024 tiles, occ 4
    constexpr int SM1 = 3 * (64 + 64) * 64 * 2;       // 48 KB
    cudaFuncSetAttribute(k_mma<64, 64, 0, 4>,
                         cudaFuncAttributeMaxDynamicSharedMemorySize, SM1);
    k_mma<64, 64, 0, 4><<<dim3(E_ / 64, B_ / 64, 4), 128, SM1>>>(
        vfn_p, wr_p, part_p, nullptr, B_, E_, D_, D_ / 4, 0);

    // 5: warp-per-row reduce + bias + relu + rownorm -> fp16 emb
    k_fuse_emb<<<B_ / 8, 256>>>(bias);

    // 6: GEMM2 128x128 tiles, occ 2, 64x64 warp tiles
    constexpr int SM2 = 3 * (128 + 128) * 64 * 2;     // 96 KB
    cudaFuncSetAttribute(k_mma<128, 128, 1, 2>,
                         cudaFuncAttributeMaxDynamicSharedMemorySize, SM2);
    const size_t off2 = (size_t)out_size / 2;
    k_mma<128, 128, 1, 2><<<dim3(NN_ / 128, B_ / 128), 128, SM2>>>(
        emb_p, nwn_p, out, pe_p, B_, NN_, E_, E_, off2);
}

// round 17
// speedup vs baseline: 1.0712x; 1.0186x over previous
#include <cuda_runtime.h>
#include <cuda_fp16.h>
#include <cstdint>

#define B_   2048
#define D_   4096
#define E_   512
#define NN_  8192
#define BN_EPS  1e-5f
#define COS_EPSF 1e-8f

// ---------------- scratch (__device__ globals; no allocations allowed) ----------------
__device__ float  g_psum[32][D_];
__device__ float  g_psq [32][D_];
__device__ float  g_scale[D_];
__device__ float  g_shift[D_];
__device__ __half g_vfn[B_ * D_];       // 17 MB (fp16 BN output)
__device__ float  g_pe [B_];
__device__ __half g_emb[B_ * E_];       // 2 MB (normalized, fp16)
__device__ __half g_nwn[NN_ * E_];      // 8 MB (normalized, fp16)
__device__ __half g_wr [E_ * D_];       // 4 MB (fp16 W)
__device__ float  g_part[4][B_ * E_];   // 16 MB split-K partials (fp32)

// ---------------- helpers ----------------
__device__ __forceinline__ void cp16(uint32_t dst, const void* src) {
    asm volatile("cp.async.cg.shared.global [%0], [%1], 16;" :: "r"(dst), "l"(src));
}
#define SW128(o) ((o) ^ (((o) >> 3) & 0x70))

#define LDSM4(r0, r1, r2, r3, a) \
    asm volatile("ldmatrix.sync.aligned.m8n8.x4.shared.b16 {%0,%1,%2,%3}, [%4];" \
                 : "=r"(r0), "=r"(r1), "=r"(r2), "=r"(r3) : "r"(a))

#define MMA16(d, av, b0v, b1v) \
    asm volatile("mma.sync.aligned.m16n8k16.row.col.f32.f16.f16.f32 " \
                 "{%0,%1,%2,%3}, {%4,%5,%6,%7}, {%8,%9}, {%0,%1,%2,%3};" \
                 : "+f"((d)[0]), "+f"((d)[1]), "+f"((d)[2]), "+f"((d)[3]) \
                 : "r"((av)[0]), "r"((av)[1]), "r"((av)[2]), "r"((av)[3]), \
                   "r"(b0v), "r"(b1v))

__device__ __forceinline__ uint32_t h2pack(float a, float b) {
    const __half2 h = __floats2half2_rn(a, b);
    return *reinterpret_cast<const uint32_t*>(&h);
}

// ------- prep pass: BN stats [0,512) | W->fp16 [512,1536) | nwn norm [1536,2560) -----
// stats: latency-bound (MLP 8); W/nwn: streaming. nwn uses warp-per-row, shfl-only.
__global__ void __launch_bounds__(256) k_prep(const float* __restrict__ vf,
                                              const float4* __restrict__ W,
                                              __half* __restrict__ Wr,
                                              const float4* __restrict__ nwfs,
                                              __half* __restrict__ nwn) {
    const int t = threadIdx.x;
    if (blockIdx.x < 512) {
        const int bid = blockIdx.x;
        const int c = (bid & 15) * 256 + t;
        const int chunk = bid >> 4;              // 0..31
        const int r0 = chunk * 64;
        float s = 0.f, q = 0.f;
        #pragma unroll 8
        for (int r = 0; r < 64; r++) {
            float v = vf[(size_t)(r0 + r) * D_ + c];
            s += v; q += v * v;
        }
        g_psum[chunk][c] = s;
        g_psq [chunk][c] = q;
    } else if (blockIdx.x < 1536) {
        const int gl = (blockIdx.x - 512) * 256 + t;   // 8 floats per thread
        const float4 v0 = __ldcs(&W[gl * 2]), v1 = __ldcs(&W[gl * 2 + 1]);
        uint4 o;
        o.x = h2pack(v0.x, v0.y); o.y = h2pack(v0.z, v0.w);
        o.z = h2pack(v1.x, v1.y); o.w = h2pack(v1.z, v1.w);
        ((uint4*)Wr)[gl] = o;
    } else {
        // warp-per-row: 8 rows per block, 32 threads own a 512-float row (4 float4 each)
        const int lane = t & 31;
        const int row = (blockIdx.x - 1536) * 8 + (t >> 5);
        const float4* src = nwfs + (size_t)row * 128;
        float4 v[4];
        #pragma unroll
        for (int j = 0; j < 4; j++) v[j] = __ldcs(&src[lane + j * 32]);
        float s = 0.f;
        #pragma unroll
        for (int j = 0; j < 4; j++)
            s += v[j].x * v[j].x + v[j].y * v[j].y + v[j].z * v[j].z + v[j].w * v[j].w;
        #pragma unroll
        for (int o = 16; o; o >>= 1) s += __shfl_xor_sync(0xffffffffu, s, o);
        const float inv = 1.0f / fmaxf(sqrtf(s), COS_EPSF);
        uint2* dst = (uint2*)(nwn + (size_t)row * E_);
        #pragma unroll
        for (int j = 0; j < 4; j++) {
            uint2 o;
            o.x = h2pack(v[j].x * inv, v[j].y * inv);
            o.y = h2pack(v[j].z * inv, v[j].w * inv);
            dst[lane + j * 32] = o;
        }
    }
}

__global__ void k_stats_final(const float* __restrict__ gamma,
                              const float* __restrict__ beta) {
    const int c = blockIdx.x * 256 + threadIdx.x;
    float s = 0.f, q = 0.f;
    #pragma unroll
    for (int i = 0; i < 32; i++) { s += g_psum[i][c]; q += g_psq[i][c]; }
    const float mean = s * (1.0f / B_);
    const float var  = q * (1.0f / B_) - mean * mean;
    const float sc   = gamma[c] * rsqrtf(var + BN_EPS);
    g_scale[c] = sc;
    g_shift[c] = beta[c] - mean * sc;
}

// ---------------- fused BN apply + p_e (row cosine); stores fp16 vfn -----------------
__global__ void __launch_bounds__(256) k_bn_pe(const float* __restrict__ vf,
                                               const float* __restrict__ p) {
    const int row = blockIdx.x;
    const int t = threadIdx.x;
    const float4* v4  = (const float4*)(vf + (size_t)row * D_);
    const float4* p4  = (const float4*)(p  + (size_t)row * D_);
    const float4* sc4 = (const float4*)g_scale;
    const float4* sh4 = (const float4*)g_shift;
    uint2* o2 = (uint2*)(g_vfn + (size_t)row * D_);

    // hoist all main-stream loads (MLP 16)
    float4 va[4], pa[4];
    #pragma unroll
    for (int u = 0; u < 4; u++) va[u] = __ldcs(&v4[t + u * 256]);
    #pragma unroll
    for (int u = 0; u < 4; u++) pa[u] = __ldcs(&p4[t + u * 256]);

    float dot = 0.f, nv = 0.f, np = 0.f;
    #pragma unroll
    for (int u = 0; u < 4; u++) {
        const int i0 = t + u * 256;
        const float4 sa = sc4[i0], ha = sh4[i0];
        float4 x;
        x.x = va[u].x * sa.x + ha.x; x.y = va[u].y * sa.y + ha.y;
        x.z = va[u].z * sa.z + ha.z; x.w = va[u].w * sa.w + ha.w;
        uint2 r;
        r.x = h2pack(x.x, x.y); r.y = h2pack(x.z, x.w);
        o2[i0] = r;
        dot += x.x * pa[u].x + x.y * pa[u].y + x.z * pa[u].z + x.w * pa[u].w;
        nv  += x.x * x.x + x.y * x.y + x.z * x.z + x.w * x.w;
        np  += pa[u].x * pa[u].x + pa[u].y * pa[u].y
             + pa[u].z * pa[u].z + pa[u].w * pa[u].w;
    }
    #pragma unroll
    for (int o = 16; o; o >>= 1) {
        dot += __shfl_down_sync(0xffffffffu, dot, o);
        nv  += __shfl_down_sync(0xffffffffu, nv,  o);
        np  += __shfl_down_sync(0xffffffffu, np,  o);
    }
    __shared__ float sd[8], sn[8], sp[8];
    const int lane = t & 31, w = t >> 5;
    if (lane == 0) { sd[w] = dot; sn[w] = nv; sp[w] = np; }
    __syncthreads();
    if (t == 0) {
        float Dv = 0.f, NV = 0.f, NP = 0.f;
        #pragma unroll
        for (int i = 0; i < 8; i++) { Dv += sd[i]; NV += sn[i]; NP += sp[i]; }
        g_pe[row] = Dv / (fmaxf(sqrtf(NV), COS_EPSF) * fmaxf(sqrtf(NP), COS_EPSF));
    }
}

// ------ split-K(4) reduce + bias + relu + rownorm -> fp16 g_emb (warp-per-row) -------
__global__ void __launch_bounds__(256) k_fuse_emb(const float* __restrict__ bias) {
    const int t = threadIdx.x;
    const int lane = t & 31;
    const int row = blockIdx.x * 8 + (t >> 5);     // 8 rows per block
    const size_t base = (size_t)row * E_;

    float4 v[4][4];
    #pragma unroll
    for (int p = 0; p < 4; p++) {
        const float4* src = (const float4*)(g_part[p] + base);
        #pragma unroll
        for (int j = 0; j < 4; j++)
            v[p][j] = __ldcs(&src[lane + j * 32]);
    }
    float4 s[4];
    #pragma unroll
    for (int j = 0; j < 4; j++) {
        s[j].x = v[0][j].x + v[1][j].x + v[2][j].x + v[3][j].x;
        s[j].y = v[0][j].y + v[1][j].y + v[2][j].y + v[3][j].y;
        s[j].z = v[0][j].z + v[1][j].z + v[2][j].z + v[3][j].z;
        s[j].w = v[0][j].w + v[1][j].w + v[2][j].w + v[3][j].w;
    }
    float nrm = 0.f;
    #pragma unroll
    for (int j = 0; j < 4; j++) {
        const float4 bq = ((const float4*)bias)[lane + j * 32];
        s[j].x = fmaxf(s[j].x + bq.x, 0.f);
        s[j].y = fmaxf(s[j].y + bq.y, 0.f);
        s[j].z = fmaxf(s[j].z + bq.z, 0.f);
        s[j].w = fmaxf(s[j].w + bq.w, 0.f);
        nrm += s[j].x * s[j].x + s[j].y * s[j].y + s[j].z * s[j].z + s[j].w * s[j].w;
    }
    #pragma unroll
    for (int o = 16; o; o >>= 1) nrm += __shfl_xor_sync(0xffffffffu, nrm, o);
    const float inv = 1.0f / fmaxf(sqrtf(nrm), COS_EPSF);
    #pragma unroll
    for (int j = 0; j < 4; j++) {
        uint2 o;
        o.x = h2pack(s[j].x * inv, s[j].y * inv);
        o.y = h2pack(s[j].z * inv, s[j].w * inv);
        ((uint2*)(g_emb + base))[lane + j * 32] = o;
    }
}

// ---------------- fp16 mma.sync GEMM, templated tile -------------------------------
// 4 warps (128 thr), 2x2 warp grid, warp tile (BM/2)x(BN/2), BK=64, 3 stages.
// EPI 0: split-K partial store. EPI 1: out=C (+ pe broadcast), streaming stores.
template<int BM, int BN, int EPI, int OCC>
__global__ void __launch_bounds__(128, OCC)
k_mma(const __half* __restrict__ A, const __half* __restrict__ Bm,
      float* __restrict__ out, const float* __restrict__ pe,
      int M, int N, int K, int kcnt, size_t off2)
{
    constexpr int BK = 64, STAGES = 3, T = 128;
    constexpr int WM = BM / 2, WN = BN / 2;
    constexpr int MT = WM / 16, NT = WN / 8;
    constexpr int ABYTES = BM * BK * 2;
    constexpr int BBYTES = BN * BK * 2;

    extern __shared__ char smem[];
    const uint32_t smA = (uint32_t)__cvta_generic_to_shared(smem);
    const uint32_t smB = smA + STAGES * ABYTES;

    const int t = threadIdx.x, lane = t & 31, warp = t >> 5;
    const int wm = warp >> 1, wn = warp & 1;
    const int m0 = blockIdx.y * BM, n0 = blockIdx.x * BN;
    int k0 = 0;
    if (EPI == 0) { k0 = blockIdx.z * kcnt; out += (size_t)blockIdx.z * M * N; }

    const uint32_t xorv = (uint32_t)(lane & 7) * 16u;
    uint32_t aoff[MT], boff[NT / 2], acx[4], bcx[4];
    #pragma unroll
    for (int mt = 0; mt < MT; mt++)
        aoff[mt] = (uint32_t)((wm * WM + mt * 16 + (lane & 15)) * 128);
    #pragma unroll
    for (int p = 0; p < NT / 2; p++)
        boff[p] = (uint32_t)((wn * WN + p * 16 + (lane & 7) + ((lane & 16) >> 1)) * 128);
    #pragma unroll
    for (int ks = 0; ks < 4; ks++) {
        acx[ks] = ((uint32_t)(ks * 32) + (uint32_t)(lane & 16)) ^ xorv;
        bcx[ks] = ((uint32_t)(ks * 32) + (uint32_t)((lane & 8) << 1)) ^ xorv;
    }

    float acc[MT][NT][4];
    #pragma unroll
    for (int i = 0; i < MT; i++)
        #pragma unroll
        for (int j = 0; j < NT; j++)
            #pragma unroll
            for (int q = 0; q < 4; q++) acc[i][j][q] = 0.f;

    auto load_tile = [&](int stage, int kt) {
        const int kk = k0 + kt * BK;
        #pragma unroll
        for (int f = t; f < BM * 8; f += T) {
            const int r = f >> 3, c = f & 7;
            cp16(smA + (uint32_t)stage * ABYTES + SW128((uint32_t)(r * 128 + c * 16)),
                 A + (size_t)(m0 + r) * K + kk + c * 8);
        }
        #pragma unroll
        for (int f = t; f < BN * 8; f += T) {
            const int r = f >> 3, c = f & 7;
            cp16(smB + (uint32_t)stage * BBYTES + SW128((uint32_t)(r * 128 + c * 16)),
                 Bm + (size_t)(n0 + r) * K + kk + c * 8);
        }
        asm volatile("cp.async.commit_group;" ::: "memory");
    };

    const int KT = kcnt / BK;
    #pragma unroll
    for (int s = 0; s < STAGES - 1; s++) load_tile(s, s);

    #pragma unroll 1
    for (int kt = 0; kt < KT; kt++) {
        const int st = kt % STAGES;
        asm volatile("cp.async.wait_group %0;" :: "n"(STAGES - 2));
        __syncthreads();
        if (kt + STAGES - 1 < KT)
            load_tile((kt + STAGES - 1) % STAGES, kt + STAGES - 1);
        else
            asm volatile("cp.async.commit_group;" ::: "memory");

        const uint32_t aB = smA + (uint32_t)st * ABYTES;
        const uint32_t bB = smB + (uint32_t)st * BBYTES;
        #pragma unroll
        for (int ks = 0; ks < 4; ks++) {
            uint32_t a[MT][4], b[NT][2];
            #pragma unroll
            for (int mt = 0; mt < MT; mt++)
                LDSM4(a[mt][0], a[mt][1], a[mt][2], a[mt][3],
                      aB + aoff[mt] + acx[ks]);
            #pragma unroll
            for (int p = 0; p < NT / 2; p++)
                LDSM4(b[2 * p][0], b[2 * p][1], b[2 * p + 1][0], b[2 * p + 1][1],
                      bB + boff[p] + bcx[ks]);
            #pragma unroll
            for (int mt = 0; mt < MT; mt++)
                #pragma unroll
                for (int nt = 0; nt < NT; nt++)
                    MMA16(acc[mt][nt], a[mt], b[nt][0], b[nt][1]);
        }
    }

    // epilogue
    #pragma unroll
    for (int mt = 0; mt < MT; mt++) {
        const int r = m0 + wm * WM + mt * 16 + (lane >> 2);
        float pv0 = 0.f, pv1 = 0.f;
        if (EPI == 1) { pv0 = pe[r]; pv1 = pe[r + 8]; }
        #pragma unroll
        for (int nt = 0; nt < NT; nt++) {
            const int c = n0 + wn * WN + nt * 8 + 2 * (lane & 3);
            if (EPI == 0) {
                *(float2*)(out + (size_t)r * N + c) =
                    make_float2(acc[mt][nt][0], acc[mt][nt][1]);
                *(float2*)(out + (size_t)(r + 8) * N + c) =
                    make_float2(acc[mt][nt][2], acc[mt][nt][3]);
            } else {
                __stcs((float2*)(out + (size_t)r * N + c),
                       make_float2(acc[mt][nt][0], acc[mt][nt][1]));
                __stcs((float2*)(out + (size_t)(r + 8) * N + c),
                       make_float2(acc[mt][nt][2], acc[mt][nt][3]));
                __stcs((float2*)(out + off2 + (size_t)r * N + c), make_float2(pv0, pv0));
                __stcs((float2*)(out + off2 + (size_t)(r + 8) * N + c), make_float2(pv1, pv1));
            }
        }
    }
}

// ---------------- launch ----------------
extern "C" void kernel_launch(void* const* d_in, const int* in_sizes, int n_in,
                              void* d_out, int out_size)
{
    const float* vf    = (const float*)d_in[0];
    const float* pwfs  = (const float*)d_in[1];
    const float* nwfs  = (const float*)d_in[2];
    const float* gamma = (const float*)d_in[3];
    const float* beta  = (const float*)d_in[4];
    const float* W     = (const float*)d_in[5];
    const float* bias  = (const float*)d_in[6];
    float* out = (float*)d_out;

    __half *vfn_p, *emb_p, *nwn_p, *wr_p;
    float *pe_p, *part_p;
    cudaGetSymbolAddress((void**)&vfn_p,  g_vfn);
    cudaGetSymbolAddress((void**)&emb_p,  g_emb);
    cudaGetSymbolAddress((void**)&nwn_p,  g_nwn);
    cudaGetSymbolAddress((void**)&pe_p,   g_pe);
    cudaGetSymbolAddress((void**)&wr_p,   g_wr);
    cudaGetSymbolAddress((void**)&part_p, g_part);

    // 1: prep — BN stats (MLP 8) co-resident with W->fp16 + nwn warp-per-row rownorm
    k_prep<<<512 + 1024 + 1024, 256>>>(vf, (const float4*)W, wr_p,
                                       (const float4*)nwfs, nwn_p);
    // 2: BN finalize
    k_stats_final<<<D_ / 256, 256>>>(gamma, beta);
    // 3: BN apply (fp16 store) + p_e
    k_bn_pe<<<B_, 256>>>(vf, pwfs);

    // 4: GEMM1 64x64 tiles, split-K=4 -> 1024 tiles, occ 4
    constexpr int SM1 = 3 * (64 + 64) * 64 * 2;       // 48 KB
    cudaFuncSetAttribute(k_mma<64, 64, 0, 4>,
                         cudaFuncAttributeMaxDynamicSharedMemorySize, SM1);
    k_mma<64, 64, 0, 4><<<dim3(E_ / 64, B_ / 64, 4), 128, SM1>>>(
        vfn_p, wr_p, part_p, nullptr, B_, E_, D_, D_ / 4, 0);

    // 5: warp-per-row reduce + bias + relu + rownorm -> fp16 emb
    k_fuse_emb<<<B_ / 8, 256>>>(bias);

    // 6: GEMM2 128x128 tiles, occ 2, 64x64 warp tiles
    constexpr int SM2 = 3 * (128 + 128) * 64 * 2;     // 96 KB
    cudaFuncSetAttribute(k_mma<128, 128, 1, 2>,
                         cudaFuncAttributeMaxDynamicSharedMemorySize, SM2);
    const size_t off2 = (size_t)out_size / 2;
    k_mma<128, 128, 1, 2><<<dim3(NN_ / 128, B_ / 128), 128, SM2>>>(
        emb_p, nwn_p, out, pe_p, B_, NN_, E_, E_, off2);
}